// round 7
// baseline (speedup 1.0000x reference)
#include <cuda_runtime.h>
#include <math.h>
#include <cstdint>

#define NB    8
#define DIM   256
#define YD    4096
#define HH    8
#define INNER 512
#define WW    256
#define ASCALE 0.125f

// ---------------- mma.sync / ldmatrix helpers (arch-agnostic, sm_80+) ------
__device__ __forceinline__ uint32_t smem_u32(const void* p) {
    uint32_t a;
    asm("{ .reg .u64 tmp; cvta.to.shared.u64 tmp, %1; cvt.u32.u64 %0, tmp; }"
        : "=r"(a) : "l"(p));
    return a;
}
#define LDSM_X4(r0, r1, r2, r3, addr) \
    asm volatile("ldmatrix.sync.aligned.m8n8.x4.shared.b16 {%0,%1,%2,%3}, [%4];" \
        : "=r"(r0), "=r"(r1), "=r"(r2), "=r"(r3) : "r"(addr))

__device__ __forceinline__ void mma_bf16(float c[4], const uint32_t a[4], const uint32_t b[2]) {
    asm volatile("mma.sync.aligned.m16n8k16.row.col.f32.bf16.bf16.f32 "
        "{%0,%1,%2,%3}, {%4,%5,%6,%7}, {%8,%9}, {%0,%1,%2,%3};"
        : "+f"(c[0]), "+f"(c[1]), "+f"(c[2]), "+f"(c[3])
        : "r"(a[0]), "r"(a[1]), "r"(a[2]), "r"(a[3]), "r"(b[0]), "r"(b[1]));
}

// split fp32 pair -> hi (truncated bf16) pair + lo (bf16 of residual) pair.
__device__ __forceinline__ void cvt_pair(float a, float b, uint32_t& hi2, uint32_t& lo2) {
    uint32_t ua = __float_as_uint(a), ub = __float_as_uint(b);
    hi2 = __byte_perm(ua, ub, 0x7632);
    float ra = a - __uint_as_float(ua & 0xffff0000u);
    float rb = b - __uint_as_float(ub & 0xffff0000u);
    asm("cvt.rn.bf16x2.f32 %0, %1, %2;" : "=r"(lo2) : "f"(rb), "f"(ra));
}

// ---------------- scratch ----------------
__device__ float g_Q0[NB * INNER * YD];
__device__ float g_Q1[NB * INNER * YD];
__device__ float g_KV0[NB * 2 * INNER * WW];
__device__ float g_KV1[NB * 2 * INNER * WW];
__device__ float g_KVp0[NB * 2 * INNER * WW];   // split-K partials
__device__ float g_KVp1[NB * 2 * INNER * WW];
__device__ float g_O0[(size_t)NB * YD * INNER];
__device__ float g_O1[(size_t)NB * YD * INNER];

// GEMM SMEM: 128 rows x 32 bf16, padded to 40 (80B = 5x16B), double buffered
#define SROW  40
#define ABUF  (128 * SROW * 2)     // 10240 B per array
#define STAGE (4 * ABUF)           // Ahi, Alo, Bhi, Blo = 40960 B
#define GEMM_DSMEM (2 * STAGE)     // 81920 B

// row-pattern prefetch/commit: thread t covers row=t>>1, 16 consecutive k at (t&1)*16
__device__ __forceinline__ void pref_rows(const float* __restrict__ src, size_t ld,
                                          int t, float4 v[4]) {
    int row = t >> 1, ks = (t & 1) * 16;
    const float4* p = (const float4*)(src + (size_t)row * ld + ks);
    v[0] = p[0]; v[1] = p[1]; v[2] = p[2]; v[3] = p[3];
}
__device__ __forceinline__ void commit_rows(char* hiB, char* loB, int t, const float4 v[4]) {
    int row = t >> 1, ks = (t & 1) * 16;
    uint32_t h[8], l[8];
    cvt_pair(v[0].x, v[0].y, h[0], l[0]); cvt_pair(v[0].z, v[0].w, h[1], l[1]);
    cvt_pair(v[1].x, v[1].y, h[2], l[2]); cvt_pair(v[1].z, v[1].w, h[3], l[3]);
    cvt_pair(v[2].x, v[2].y, h[4], l[4]); cvt_pair(v[2].z, v[2].w, h[5], l[5]);
    cvt_pair(v[3].x, v[3].y, h[6], l[6]); cvt_pair(v[3].z, v[3].w, h[7], l[7]);
    char* dh = hiB + row * (SROW * 2) + ks * 2;
    char* dl = loB + row * (SROW * 2) + ks * 2;
    *(uint4*)dh       = make_uint4(h[0], h[1], h[2], h[3]);
    *((uint4*)dh + 1) = make_uint4(h[4], h[5], h[6], h[7]);
    *(uint4*)dl       = make_uint4(l[0], l[1], l[2], l[3]);
    *((uint4*)dl + 1) = make_uint4(l[4], l[5], l[6], l[7]);
}

// One BK=32 chunk (3-pass hi/lo). Restructured for low live-register count.
__device__ __forceinline__ void mma_chunk2(
    uint32_t base, float acc[4][4][4], int lane, int wm, int wn)
{
    const uint32_t aHi = base, aLo = base + ABUF;
    const uint32_t bHi = base + 2 * ABUF, bLo = base + 3 * ABUF;
    const int arow  = lane & 15;
    const int acol8 = (lane >> 4) * 8;
    const int brow  = ((lane >> 4) & 1) * 8 + (lane & 7);
    const int bcol8 = ((lane >> 3) & 1) * 8;
#pragma unroll
    for (int ks = 0; ks < 32; ks += 16) {
        uint32_t bh[4][2], bl[4][2];
#pragma unroll
        for (int np = 0; np < 2; np++) {
            uint32_t off = (uint32_t)(wn + np * 16 + brow) * (SROW * 2) + (ks + bcol8) * 2;
            LDSM_X4(bh[np*2][0], bh[np*2][1], bh[np*2+1][0], bh[np*2+1][1], bHi + off);
            LDSM_X4(bl[np*2][0], bl[np*2][1], bl[np*2+1][0], bl[np*2+1][1], bLo + off);
        }
#pragma unroll
        for (int mt = 0; mt < 4; mt++) {
            uint32_t ah[4], al[4];
            uint32_t off = (uint32_t)(wm + mt * 16 + arow) * (SROW * 2) + (ks + acol8) * 2;
            LDSM_X4(ah[0], ah[1], ah[2], ah[3], aHi + off);
            LDSM_X4(al[0], al[1], al[2], al[3], aLo + off);
#pragma unroll
            for (int nt = 0; nt < 4; nt++) {
                mma_bf16(acc[mt][nt], ah, bh[nt]);
                mma_bf16(acc[mt][nt], ah, bl[nt]);
                mma_bf16(acc[mt][nt], al, bh[nt]);
            }
        }
    }
}

__device__ __forceinline__ void store_c(
    float* C, size_t ldc, int m0, int n0,
    float acc[4][4][4], int lane, int wm, int wn)
{
    int g = lane >> 2, tt = lane & 3;
#pragma unroll
    for (int mt = 0; mt < 4; mt++) {
        int r = m0 + wm + mt * 16 + g;
#pragma unroll
        for (int nt = 0; nt < 4; nt++) {
            int cc = n0 + wn + nt * 8 + 2 * tt;
            *(float2*)&C[(size_t)r * ldc + cc]       = make_float2(acc[mt][nt][0], acc[mt][nt][1]);
            *(float2*)&C[(size_t)(r + 8) * ldc + cc] = make_float2(acc[mt][nt][2], acc[mt][nt][3]);
        }
    }
}

#define GEMM_PROLOG \
    extern __shared__ char smg[]; \
    const uint32_t sbase = smem_u32(smg); \
    const int t = threadIdx.x, lane = t & 31, wid = t >> 5; \
    const int wm = (wid & 1) * 64, wn = (wid >> 1) * 32; \
    float acc[4][4][4]; \
    _Pragma("unroll") for (int i = 0; i < 4; i++) \
    _Pragma("unroll") for (int j = 0; j < 4; j++) \
    _Pragma("unroll") for (int q = 0; q < 4; q++) acc[i][j][q] = 0.f;

// =====================================================================
// Q projection. M=512,K=256,N=4096. grid(32,4,16), 256 thr, 8 chunks.
// =====================================================================
__global__ __launch_bounds__(256, 2) void qproj_tc(
    const float* __restrict__ A0, const float* __restrict__ X0, float* __restrict__ C0,
    const float* __restrict__ A1, const float* __restrict__ X1, float* __restrict__ C1)
{
    GEMM_PROLOG
    const int z = blockIdx.z, b = z & 7;
    const int m0 = blockIdx.y * 128, n0 = blockIdx.x * 128;
    const float* A = ((z < 8) ? A0 : A1) + (size_t)m0 * DIM;
    const float* X = ((z < 8) ? X0 : X1) + (size_t)b * DIM * YD;
    float*       C = ((z < 8) ? C0 : C1) + (size_t)b * INNER * YD;

    const int k2 = t >> 4, nl0 = t & 15;
    float4 av[4]; float pa[8], pb[8];

    // prefetch + commit chunk 0
    pref_rows(A, DIM, t, av);
    {
        const float* xr0 = &X[(size_t)(2 * k2) * YD + n0];
        const float* xr1 = xr0 + YD;
#pragma unroll
        for (int j = 0; j < 8; j++) { pa[j] = xr0[nl0 + 16 * j]; pb[j] = xr1[nl0 + 16 * j]; }
    }
    commit_rows(smg, smg + ABUF, t, av);
#pragma unroll
    for (int j = 0; j < 8; j++) {
        uint32_t h, l; cvt_pair(pa[j], pb[j], h, l);
        int nl = nl0 + 16 * j;
        *(uint32_t*)(smg + 2 * ABUF + nl * (SROW * 2) + k2 * 4) = h;
        *(uint32_t*)(smg + 3 * ABUF + nl * (SROW * 2) + k2 * 4) = l;
    }
    __syncthreads();

    for (int c = 0; c < 8; c++) {
        if (c < 7) {
            int k0 = (c + 1) * 32;
            pref_rows(A + k0, DIM, t, av);
            const float* xr0 = &X[(size_t)(k0 + 2 * k2) * YD + n0];
            const float* xr1 = xr0 + YD;
#pragma unroll
            for (int j = 0; j < 8; j++) { pa[j] = xr0[nl0 + 16 * j]; pb[j] = xr1[nl0 + 16 * j]; }
        }
        mma_chunk2(sbase + (c & 1) * STAGE, acc, lane, wm, wn);
        if (c < 7) {
            char* st = smg + ((c + 1) & 1) * STAGE;
            commit_rows(st, st + ABUF, t, av);
#pragma unroll
            for (int j = 0; j < 8; j++) {
                uint32_t h, l; cvt_pair(pa[j], pb[j], h, l);
                int nl = nl0 + 16 * j;
                *(uint32_t*)(st + 2 * ABUF + nl * (SROW * 2) + k2 * 4) = h;
                *(uint32_t*)(st + 3 * ABUF + nl * (SROW * 2) + k2 * 4) = l;
            }
        }
        __syncthreads();
    }
    store_c(C, YD, m0, n0, acc, lane, wm, wn);
}

// =====================================================================
// KV projection, split-K x2. M=1024,K=4096(x2 halves),N(w)=256.
// grid(4=2w x 2ksplit, 8, 16), 256 thr, 64 chunks. ksel=1 -> partial buf.
// =====================================================================
__global__ __launch_bounds__(256, 2) void kvproj_tc(
    const float* __restrict__ W0, const float* __restrict__ X0,
    float* __restrict__ C0, float* __restrict__ P0,
    const float* __restrict__ W1, const float* __restrict__ X1,
    float* __restrict__ C1, float* __restrict__ P1)
{
    GEMM_PROLOG
    const int z = blockIdx.z, b = z & 7;
    const int wsel = blockIdx.x & 1, ksel = blockIdx.x >> 1;
    const int m0 = blockIdx.y * 128, w0 = wsel * 128;
    const int K = DIM * 16;
    const float* A  = ((z < 8) ? W0 : W1) + (size_t)m0 * K;
    const float* xp = ((z < 8) ? X0 : X1) + (size_t)b * DIM * YD;
    float* C = ((z < 8) ? (ksel ? P0 : C0) : (ksel ? P1 : C1)) + (size_t)b * 2 * INNER * WW;
    const int gbase = ksel * 64;   // global chunk offset

    const int p = t >> 7, wl = t & 127;
    float4 av[4], bv[4];

    // chunk 0
    pref_rows(A + (size_t)gbase * 32, K, t, av);
    {
        const float4* src = (const float4*)(xp + (size_t)(2 * gbase + p) * YD + (size_t)(w0 + wl) * 16);
        bv[0] = src[0]; bv[1] = src[1]; bv[2] = src[2]; bv[3] = src[3];
    }
    commit_rows(smg, smg + ABUF, t, av);
    {
        uint32_t h[8], l[8];
        cvt_pair(bv[0].x, bv[0].y, h[0], l[0]); cvt_pair(bv[0].z, bv[0].w, h[1], l[1]);
        cvt_pair(bv[1].x, bv[1].y, h[2], l[2]); cvt_pair(bv[1].z, bv[1].w, h[3], l[3]);
        cvt_pair(bv[2].x, bv[2].y, h[4], l[4]); cvt_pair(bv[2].z, bv[2].w, h[5], l[5]);
        cvt_pair(bv[3].x, bv[3].y, h[6], l[6]); cvt_pair(bv[3].z, bv[3].w, h[7], l[7]);
        char* dh = smg + 2 * ABUF + wl * (SROW * 2) + p * 32;
        char* dl = smg + 3 * ABUF + wl * (SROW * 2) + p * 32;
        *(uint4*)dh       = make_uint4(h[0], h[1], h[2], h[3]);
        *((uint4*)dh + 1) = make_uint4(h[4], h[5], h[6], h[7]);
        *(uint4*)dl       = make_uint4(l[0], l[1], l[2], l[3]);
        *((uint4*)dl + 1) = make_uint4(l[4], l[5], l[6], l[7]);
    }
    __syncthreads();

    for (int c = 0; c < 64; c++) {
        if (c < 63) {
            int g = gbase + c + 1;
            pref_rows(A + (size_t)g * 32, K, t, av);
            const float4* src = (const float4*)(xp + (size_t)(2 * g + p) * YD + (size_t)(w0 + wl) * 16);
            bv[0] = src[0]; bv[1] = src[1]; bv[2] = src[2]; bv[3] = src[3];
        }
        mma_chunk2(sbase + (c & 1) * STAGE, acc, lane, wm, wn);
        if (c < 63) {
            char* st = smg + ((c + 1) & 1) * STAGE;
            commit_rows(st, st + ABUF, t, av);
            uint32_t h[8], l[8];
            cvt_pair(bv[0].x, bv[0].y, h[0], l[0]); cvt_pair(bv[0].z, bv[0].w, h[1], l[1]);
            cvt_pair(bv[1].x, bv[1].y, h[2], l[2]); cvt_pair(bv[1].z, bv[1].w, h[3], l[3]);
            cvt_pair(bv[2].x, bv[2].y, h[4], l[4]); cvt_pair(bv[2].z, bv[2].w, h[5], l[5]);
            cvt_pair(bv[3].x, bv[3].y, h[6], l[6]); cvt_pair(bv[3].z, bv[3].w, h[7], l[7]);
            char* dh = st + 2 * ABUF + wl * (SROW * 2) + p * 32;
            char* dl = st + 3 * ABUF + wl * (SROW * 2) + p * 32;
            *(uint4*)dh       = make_uint4(h[0], h[1], h[2], h[3]);
            *((uint4*)dh + 1) = make_uint4(h[4], h[5], h[6], h[7]);
            *(uint4*)dl       = make_uint4(l[0], l[1], l[2], l[3]);
            *((uint4*)dl + 1) = make_uint4(l[4], l[5], l[6], l[7]);
        }
        __syncthreads();
    }
    store_c(C, WW, m0, w0, acc, lane, wm, wn);
}

// KV split-K reduction: KV += KVp (both streams). 2M floats each.
__global__ __launch_bounds__(256) void kv_reduce(
    float* __restrict__ a, const float* __restrict__ pa,
    float* __restrict__ b, const float* __restrict__ pb)
{
    size_t i = ((size_t)blockIdx.x * 256 + threadIdx.x) * 4;
    float4 v0 = *(float4*)&a[i], q0 = *(const float4*)&pa[i];
    v0.x += q0.x; v0.y += q0.y; v0.z += q0.z; v0.w += q0.w;
    *(float4*)&a[i] = v0;
    float4 v1 = *(float4*)&b[i], q1 = *(const float4*)&pb[i];
    v1.x += q1.x; v1.y += q1.y; v1.z += q1.z; v1.w += q1.w;
    *(float4*)&b[i] = v1;
}

// =====================================================================
// Attention. CTA = 64 q rows x (b,h,stream); 128 thr (4 warps x 16 rows).
// Q+K staged, QK mma, warp-local softmax, then V overlays K's SMEM.
// 92160 B dynamic smem -> 2 CTAs/SM.
// =====================================================================
#define QROW_B 144      // 72 bf16 per row
#define VROW_B 528      // 264 bf16 per row
#define ATTN_DSMEM 92160

__global__ __launch_bounds__(128, 2) void attn_tc(
    const float* __restrict__ Q0, const float* __restrict__ KVa, float* __restrict__ O0,
    const float* __restrict__ Q1, const float* __restrict__ KVb, float* __restrict__ O1)
{
    extern __shared__ char sm[];
    const int z = blockIdx.z, b = z & 7;
    const float* Q  = (z < NB) ? Q0 : Q1;
    const float* KV = (z < NB) ? KVa : KVb;
    float*       O  = (z < NB) ? O0 : O1;
    const int h  = blockIdx.y;
    const int i0 = blockIdx.x * 64;

    char* sQh = sm;           char* sQl = sm + 9216;
    char* sKh = sm + 18432;   char* sKl = sm + 18432 + 36864;
    char* sVh = sm + 18432;   char* sVl = sm + 18432 + 33792;   // overlays K

    const int t = threadIdx.x, lane = t & 31, wid = t >> 5;

    const float* Qb = Q + ((size_t)b * INNER + h * 64) * YD + i0;
    const float* Kb = KV + ((size_t)b * 1024 + h * 64) * WW;
    const float* Vb = KV + ((size_t)b * 1024 + 512 + h * 64) * WW;

    // ---- stage Q [i][d] hi/lo ----
#pragma unroll
    for (int u = 0; u < 16; u++) {
        int idx = u * 128 + t;
        int d2 = idx >> 6, i = idx & 63;
        float a = Qb[(size_t)(2 * d2) * YD + i];
        float c = Qb[(size_t)(2 * d2 + 1) * YD + i];
        uint32_t hh, ll; cvt_pair(a, c, hh, ll);
        *(uint32_t*)(sQh + i * QROW_B + d2 * 4) = hh;
        *(uint32_t*)(sQl + i * QROW_B + d2 * 4) = ll;
    }
    // ---- stage K [j][d] hi/lo ----
#pragma unroll
    for (int u = 0; u < 64; u++) {
        int idx = u * 128 + t;
        int d2 = idx >> 8, j = idx & 255;
        float a = Kb[(size_t)(2 * d2) * WW + j];
        float c = Kb[(size_t)(2 * d2 + 1) * WW + j];
        uint32_t hh, ll; cvt_pair(a, c, hh, ll);
        *(uint32_t*)(sKh + j * QROW_B + d2 * 4) = hh;
        *(uint32_t*)(sKl + j * QROW_B + d2 * 4) = ll;
    }
    __syncthreads();

    const uint32_t uQh = smem_u32(sQh), uQl = smem_u32(sQl);
    const uint32_t uKh = smem_u32(sKh), uKl = smem_u32(sKl);

    const int arow  = lane & 15, acol8 = (lane >> 4) * 8;
    const int brow  = ((lane >> 4) & 1) * 8 + (lane & 7);
    const int bcol8 = ((lane >> 3) & 1) * 8;

    // ---- QK^T: 16 x 256 per warp ----
    float s[32][4];
#pragma unroll
    for (int nt = 0; nt < 32; nt++)
#pragma unroll
        for (int q = 0; q < 4; q++) s[nt][q] = 0.f;

#pragma unroll
    for (int kc = 0; kc < 4; kc++) {
        uint32_t ah[4], al[4];
        uint32_t aoff = (uint32_t)(wid * 16 + arow) * QROW_B + (kc * 16 + acol8) * 2;
        LDSM_X4(ah[0], ah[1], ah[2], ah[3], uQh + aoff);
        LDSM_X4(al[0], al[1], al[2], al[3], uQl + aoff);
#pragma unroll
        for (int np = 0; np < 16; np++) {
            uint32_t boff = (uint32_t)(np * 16 + brow) * QROW_B + (kc * 16 + bcol8) * 2;
            uint32_t bh[4], bl[4];
            LDSM_X4(bh[0], bh[1], bh[2], bh[3], uKh + boff);
            LDSM_X4(bl[0], bl[1], bl[2], bl[3], uKl + boff);
            mma_bf16(s[2*np],   ah, &bh[0]);
            mma_bf16(s[2*np],   ah, &bl[0]);
            mma_bf16(s[2*np],   al, &bh[0]);
            mma_bf16(s[2*np+1], ah, &bh[2]);
            mma_bf16(s[2*np+1], ah, &bl[2]);
            mma_bf16(s[2*np+1], al, &bh[2]);
        }
    }

    // ---- warp-local softmax (rows g and g+8) ----
    float mx1 = -1e30f, mx2 = -1e30f;
#pragma unroll
    for (int nt = 0; nt < 32; nt++) {
        s[nt][0] *= ASCALE; s[nt][1] *= ASCALE;
        s[nt][2] *= ASCALE; s[nt][3] *= ASCALE;
        mx1 = fmaxf(mx1, fmaxf(s[nt][0], s[nt][1]));
        mx2 = fmaxf(mx2, fmaxf(s[nt][2], s[nt][3]));
    }
    mx1 = fmaxf(mx1, __shfl_xor_sync(0xffffffffu, mx1, 1));
    mx1 = fmaxf(mx1, __shfl_xor_sync(0xffffffffu, mx1, 2));
    mx2 = fmaxf(mx2, __shfl_xor_sync(0xffffffffu, mx2, 1));
    mx2 = fmaxf(mx2, __shfl_xor_sync(0xffffffffu, mx2, 2));
    float sum1 = 0.f, sum2 = 0.f;
#pragma unroll
    for (int nt = 0; nt < 32; nt++) {
        s[nt][0] = __expf(s[nt][0] - mx1); sum1 += s[nt][0];
        s[nt][1] = __expf(s[nt][1] - mx1); sum1 += s[nt][1];
        s[nt][2] = __expf(s[nt][2] - mx2); sum2 += s[nt][2];
        s[nt][3] = __expf(s[nt][3] - mx2); sum2 += s[nt][3];
    }
    sum1 += __shfl_xor_sync(0xffffffffu, sum1, 1);
    sum1 += __shfl_xor_sync(0xffffffffu, sum1, 2);
    sum2 += __shfl_xor_sync(0xffffffffu, sum2, 1);
    sum2 += __shfl_xor_sync(0xffffffffu, sum2, 2);
    const float i1 = 1.f / sum1, i2 = 1.f / sum2;

    // ---- stage V [d][j] into K's region ----
    __syncthreads();
#pragma unroll
    for (int u = 0; u < 32; u++) {
        int idx = u * 128 + t;
        int d = idx >> 6, j4 = (idx & 63) * 4;
        float4 f = *(const float4*)&Vb[(size_t)d * WW + j4];
        uint32_t h0, l0, h1, l1;
        cvt_pair(f.x, f.y, h0, l0); cvt_pair(f.z, f.w, h1, l1);
        *(uint2*)(sVh + d * VROW_B + j4 * 2) = make_uint2(h0, h1);
        *(uint2*)(sVl + d * VROW_B + j4 * 2) = make_uint2(l0, l1);
    }
    __syncthreads();

    const uint32_t uVh = smem_u32(sVh), uVl = smem_u32(sVl);

    // ---- P @ V ----
    float o[8][4];
#pragma unroll
    for (int dt = 0; dt < 8; dt++)
#pragma unroll
        for (int q = 0; q < 4; q++) o[dt][q] = 0.f;

#pragma unroll
    for (int kc = 0; kc < 16; kc++) {
        uint32_t ph[4], pl[4];
        cvt_pair(s[2*kc][0]   * i1, s[2*kc][1]   * i1, ph[0], pl[0]);
        cvt_pair(s[2*kc][2]   * i2, s[2*kc][3]   * i2, ph[1], pl[1]);
        cvt_pair(s[2*kc+1][0] * i1, s[2*kc+1][1] * i1, ph[2], pl[2]);
        cvt_pair(s[2*kc+1][2] * i2, s[2*kc+1][3] * i2, ph[3], pl[3]);
#pragma unroll
        for (int dp = 0; dp < 4; dp++) {
            uint32_t voff = (uint32_t)(dp * 16 + brow) * VROW_B + (kc * 16 + bcol8) * 2;
            uint32_t vh[4], vl[4];
            LDSM_X4(vh[0], vh[1], vh[2], vh[3], uVh + voff);
            LDSM_X4(vl[0], vl[1], vl[2], vl[3], uVl + voff);
            mma_bf16(o[2*dp],   ph, &vh[0]);
            mma_bf16(o[2*dp],   pl, &vh[0]);
            mma_bf16(o[2*dp],   ph, &vl[0]);
            mma_bf16(o[2*dp+1], ph, &vh[2]);
            mma_bf16(o[2*dp+1], pl, &vh[2]);
            mma_bf16(o[2*dp+1], ph, &vl[2]);
        }
    }

    // ---- write O[b][y][h*64+d] ----
    const int g = lane >> 2, tt = lane & 3;
    const int y = i0 + wid * 16 + g;
    size_t rb = ((size_t)b * YD + y) * INNER + h * 64;
#pragma unroll
    for (int dt = 0; dt < 8; dt++) {
        *(float2*)&O[rb + dt * 8 + 2 * tt] = make_float2(o[dt][0], o[dt][1]);
        *(float2*)&O[rb + (size_t)8 * INNER + dt * 8 + 2 * tt] = make_float2(o[dt][2], o[dt][3]);
    }
}

// =====================================================================
// Out projection (NT, both phases) + residual fuse. grid(32,2,8), 32 chunks.
// =====================================================================
__global__ __launch_bounds__(256, 2) void outproj_tc(
    const float* __restrict__ W0, const float* __restrict__ O0,
    const float* __restrict__ W1, const float* __restrict__ O1,
    const float* __restrict__ b0, const float* __restrict__ b1,
    const float* __restrict__ x0, const float* __restrict__ x1,
    float* __restrict__ out)
{
    GEMM_PROLOG
    const int b = blockIdx.z;
    const int m0 = blockIdx.y * 128, n0 = blockIdx.x * 128;

    float4 av[4], bv[4];
    const float* Wp[2] = { W0 + (size_t)m0 * INNER, W1 + (size_t)m0 * INNER };
    const float* Op[2] = { O0 + ((size_t)b * YD + n0) * INNER,
                           O1 + ((size_t)b * YD + n0) * INNER };

    pref_rows(Wp[0], INNER, t, av);
    pref_rows(Op[0], INNER, t, bv);
    commit_rows(smg, smg + ABUF, t, av);
    commit_rows(smg + 2 * ABUF, smg + 3 * ABUF, t, bv);
    __syncthreads();

    for (int c = 0; c < 32; c++) {
        if (c < 31) {
            int cn = c + 1;
            int phs = cn >> 4, k0 = (cn & 15) * 32;
            pref_rows(Wp[phs] + k0, INNER, t, av);
            pref_rows(Op[phs] + k0, INNER, t, bv);
        }
        mma_chunk2(sbase + (c & 1) * STAGE, acc, lane, wm, wn);
        if (c < 31) {
            char* st = smg + ((c + 1) & 1) * STAGE;
            commit_rows(st, st + ABUF, t, av);
            commit_rows(st + 2 * ABUF, st + 3 * ABUF, t, bv);
        }
        __syncthreads();
    }

    const int g = lane >> 2, tt = lane & 3;
#pragma unroll
    for (int mt = 0; mt < 4; mt++) {
        int r = m0 + wm + mt * 16 + g;
        float biasA = 0.5f * (b0[r] + b1[r]);
        float biasB = 0.5f * (b0[r + 8] + b1[r + 8]);
#pragma unroll
        for (int nt = 0; nt < 4; nt++) {
            int cc = n0 + wn + nt * 8 + 2 * tt;
            size_t iA = ((size_t)b * DIM + r) * YD + cc;
            size_t iB = ((size_t)b * DIM + r + 8) * YD + cc;
            float2 xa = *(const float2*)&x0[iA], xb = *(const float2*)&x1[iA];
            float2 oo;
            oo.x = 0.5f * (acc[mt][nt][0] + xa.x + xb.x) + biasA;
            oo.y = 0.5f * (acc[mt][nt][1] + xa.y + xb.y) + biasA;
            *(float2*)&out[iA] = oo;
            xa = *(const float2*)&x0[iB]; xb = *(const float2*)&x1[iB];
            oo.x = 0.5f * (acc[mt][nt][2] + xa.x + xb.x) + biasB;
            oo.y = 0.5f * (acc[mt][nt][3] + xa.y + xb.y) + biasB;
            *(float2*)&out[iB] = oo;
        }
    }
}

// =====================================================================
extern "C" void kernel_launch(void* const* d_in, const int* in_sizes, int n_in,
                              void* d_out, int out_size)
{
    const float* x0    = (const float*)d_in[0];
    const float* x1    = (const float*)d_in[1];
    const float* Wq0   = (const float*)d_in[2];
    const float* Wkv0  = (const float*)d_in[3];
    const float* Wq1   = (const float*)d_in[4];
    const float* Wkv1  = (const float*)d_in[5];
    const float* Wout0 = (const float*)d_in[6];
    const float* bout0 = (const float*)d_in[7];
    const float* Wout1 = (const float*)d_in[8];
    const float* bout1 = (const float*)d_in[9];
    float* out = (float*)d_out;

    float *Q0, *Q1, *KV0, *KV1, *KVp0, *KVp1, *O0, *O1;
    cudaGetSymbolAddress((void**)&Q0,   g_Q0);
    cudaGetSymbolAddress((void**)&Q1,   g_Q1);
    cudaGetSymbolAddress((void**)&KV0,  g_KV0);
    cudaGetSymbolAddress((void**)&KV1,  g_KV1);
    cudaGetSymbolAddress((void**)&KVp0, g_KVp0);
    cudaGetSymbolAddress((void**)&KVp1, g_KVp1);
    cudaGetSymbolAddress((void**)&O0,   g_O0);
    cudaGetSymbolAddress((void**)&O1,   g_O1);

    cudaFuncSetAttribute(qproj_tc,   cudaFuncAttributeMaxDynamicSharedMemorySize, GEMM_DSMEM);
    cudaFuncSetAttribute(kvproj_tc,  cudaFuncAttributeMaxDynamicSharedMemorySize, GEMM_DSMEM);
    cudaFuncSetAttribute(outproj_tc, cudaFuncAttributeMaxDynamicSharedMemorySize, GEMM_DSMEM);
    cudaFuncSetAttribute(attn_tc,    cudaFuncAttributeMaxDynamicSharedMemorySize, ATTN_DSMEM);

    qproj_tc<<<dim3(YD / 128, INNER / 128, 2 * NB), 256, GEMM_DSMEM>>>(
        Wq0, x0, Q0, Wq1, x1, Q1);
    kvproj_tc<<<dim3(4, (2 * INNER) / 128, 2 * NB), 256, GEMM_DSMEM>>>(
        Wkv0, x0, KV0, KVp0, Wkv1, x1, KV1, KVp1);
    kv_reduce<<<dim3((NB * 2 * INNER * WW) / (256 * 4)), 256>>>(KV0, KVp0, KV1, KVp1);
    attn_tc<<<dim3(YD / 64, HH, 2 * NB), 128, ATTN_DSMEM>>>(
        Q0, KV1, O0, Q1, KV0, O1);
    outproj_tc<<<dim3(YD / 128, DIM / 128, NB), 256, GEMM_DSMEM>>>(
        Wout0, O0, Wout1, O1, bout0, bout1, x0, x1, out);
}

// round 8
// speedup vs baseline: 1.0190x; 1.0190x over previous
#include <cuda_runtime.h>
#include <math.h>
#include <cstdint>

#define NB    8
#define DIM   256
#define YD    4096
#define HH    8
#define INNER 512
#define WW    256
#define ASCALE 0.125f

// ---------------- mma.sync / ldmatrix helpers (arch-agnostic, sm_80+) ------
__device__ __forceinline__ uint32_t smem_u32(const void* p) {
    uint32_t a;
    asm("{ .reg .u64 tmp; cvta.to.shared.u64 tmp, %1; cvt.u32.u64 %0, tmp; }"
        : "=r"(a) : "l"(p));
    return a;
}
#define LDSM_X4(r0, r1, r2, r3, addr) \
    asm volatile("ldmatrix.sync.aligned.m8n8.x4.shared.b16 {%0,%1,%2,%3}, [%4];" \
        : "=r"(r0), "=r"(r1), "=r"(r2), "=r"(r3) : "r"(addr))

__device__ __forceinline__ void mma_bf16(float c[4], const uint32_t a[4], const uint32_t b[2]) {
    asm volatile("mma.sync.aligned.m16n8k16.row.col.f32.bf16.bf16.f32 "
        "{%0,%1,%2,%3}, {%4,%5,%6,%7}, {%8,%9}, {%0,%1,%2,%3};"
        : "+f"(c[0]), "+f"(c[1]), "+f"(c[2]), "+f"(c[3])
        : "r"(a[0]), "r"(a[1]), "r"(a[2]), "r"(a[3]), "r"(b[0]), "r"(b[1]));
}

// split fp32 pair -> hi (truncated bf16) pair + lo (bf16 of residual) pair.
__device__ __forceinline__ void cvt_pair(float a, float b, uint32_t& hi2, uint32_t& lo2) {
    uint32_t ua = __float_as_uint(a), ub = __float_as_uint(b);
    hi2 = __byte_perm(ua, ub, 0x7632);
    float ra = a - __uint_as_float(ua & 0xffff0000u);
    float rb = b - __uint_as_float(ub & 0xffff0000u);
    asm("cvt.rn.bf16x2.f32 %0, %1, %2;" : "=r"(lo2) : "f"(rb), "f"(ra));
}

// ---------------- scratch ----------------
__device__ float g_Q0[NB * INNER * YD];
__device__ float g_Q1[NB * INNER * YD];
__device__ float g_KV0[NB * 2 * INNER * WW];
__device__ float g_KV1[NB * 2 * INNER * WW];
__device__ float g_KVp0[NB * 2 * INNER * WW];   // split-K partials
__device__ float g_KVp1[NB * 2 * INNER * WW];
__device__ float g_O0[(size_t)NB * YD * INNER];
__device__ float g_O1[(size_t)NB * YD * INNER];

// GEMM SMEM: 128 rows x 32 bf16, padded to 40 (80B = 5x16B), double buffered
#define SROW  40
#define ABUF  (128 * SROW * 2)     // 10240 B per array
#define STAGE (4 * ABUF)           // Ahi, Alo, Bhi, Blo = 40960 B
#define GEMM_DSMEM (2 * STAGE)     // 81920 B

__device__ __forceinline__ void pref_rows(const float* __restrict__ src, size_t ld,
                                          int t, float4 v[4]) {
    int row = t >> 1, ks = (t & 1) * 16;
    const float4* p = (const float4*)(src + (size_t)row * ld + ks);
    v[0] = p[0]; v[1] = p[1]; v[2] = p[2]; v[3] = p[3];
}
__device__ __forceinline__ void commit_rows(char* hiB, char* loB, int t, const float4 v[4]) {
    int row = t >> 1, ks = (t & 1) * 16;
    uint32_t h[8], l[8];
    cvt_pair(v[0].x, v[0].y, h[0], l[0]); cvt_pair(v[0].z, v[0].w, h[1], l[1]);
    cvt_pair(v[1].x, v[1].y, h[2], l[2]); cvt_pair(v[1].z, v[1].w, h[3], l[3]);
    cvt_pair(v[2].x, v[2].y, h[4], l[4]); cvt_pair(v[2].z, v[2].w, h[5], l[5]);
    cvt_pair(v[3].x, v[3].y, h[6], l[6]); cvt_pair(v[3].z, v[3].w, h[7], l[7]);
    char* dh = hiB + row * (SROW * 2) + ks * 2;
    char* dl = loB + row * (SROW * 2) + ks * 2;
    *(uint4*)dh       = make_uint4(h[0], h[1], h[2], h[3]);
    *((uint4*)dh + 1) = make_uint4(h[4], h[5], h[6], h[7]);
    *(uint4*)dl       = make_uint4(l[0], l[1], l[2], l[3]);
    *((uint4*)dl + 1) = make_uint4(l[4], l[5], l[6], l[7]);
}

__device__ __forceinline__ void mma_chunk2(
    uint32_t base, float acc[4][4][4], int lane, int wm, int wn)
{
    const uint32_t aHi = base, aLo = base + ABUF;
    const uint32_t bHi = base + 2 * ABUF, bLo = base + 3 * ABUF;
    const int arow  = lane & 15;
    const int acol8 = (lane >> 4) * 8;
    const int brow  = ((lane >> 4) & 1) * 8 + (lane & 7);
    const int bcol8 = ((lane >> 3) & 1) * 8;
#pragma unroll
    for (int ks = 0; ks < 32; ks += 16) {
        uint32_t bh[4][2], bl[4][2];
#pragma unroll
        for (int np = 0; np < 2; np++) {
            uint32_t off = (uint32_t)(wn + np * 16 + brow) * (SROW * 2) + (ks + bcol8) * 2;
            LDSM_X4(bh[np*2][0], bh[np*2][1], bh[np*2+1][0], bh[np*2+1][1], bHi + off);
            LDSM_X4(bl[np*2][0], bl[np*2][1], bl[np*2+1][0], bl[np*2+1][1], bLo + off);
        }
#pragma unroll
        for (int mt = 0; mt < 4; mt++) {
            uint32_t ah[4], al[4];
            uint32_t off = (uint32_t)(wm + mt * 16 + arow) * (SROW * 2) + (ks + acol8) * 2;
            LDSM_X4(ah[0], ah[1], ah[2], ah[3], aHi + off);
            LDSM_X4(al[0], al[1], al[2], al[3], aLo + off);
#pragma unroll
            for (int nt = 0; nt < 4; nt++) {
                mma_bf16(acc[mt][nt], ah, bh[nt]);
                mma_bf16(acc[mt][nt], ah, bl[nt]);
                mma_bf16(acc[mt][nt], al, bh[nt]);
            }
        }
    }
}

__device__ __forceinline__ void store_c(
    float* C, size_t ldc, int m0, int n0,
    float acc[4][4][4], int lane, int wm, int wn)
{
    int g = lane >> 2, tt = lane & 3;
#pragma unroll
    for (int mt = 0; mt < 4; mt++) {
        int r = m0 + wm + mt * 16 + g;
#pragma unroll
        for (int nt = 0; nt < 4; nt++) {
            int cc = n0 + wn + nt * 8 + 2 * tt;
            *(float2*)&C[(size_t)r * ldc + cc]       = make_float2(acc[mt][nt][0], acc[mt][nt][1]);
            *(float2*)&C[(size_t)(r + 8) * ldc + cc] = make_float2(acc[mt][nt][2], acc[mt][nt][3]);
        }
    }
}

#define GEMM_PROLOG \
    extern __shared__ char smg[]; \
    const uint32_t sbase = smem_u32(smg); \
    const int t = threadIdx.x, lane = t & 31, wid = t >> 5; \
    const int wm = (wid & 1) * 64, wn = (wid >> 1) * 32; \
    float acc[4][4][4]; \
    _Pragma("unroll") for (int i = 0; i < 4; i++) \
    _Pragma("unroll") for (int j = 0; j < 4; j++) \
    _Pragma("unroll") for (int q = 0; q < 4; q++) acc[i][j][q] = 0.f;

// =====================================================================
// Q projection. M=512,K=256,N=4096. grid(32,4,16), 256 thr, 8 chunks.
// =====================================================================
__global__ __launch_bounds__(256, 2) void qproj_tc(
    const float* __restrict__ A0, const float* __restrict__ X0, float* __restrict__ C0,
    const float* __restrict__ A1, const float* __restrict__ X1, float* __restrict__ C1)
{
    GEMM_PROLOG
    const int z = blockIdx.z, b = z & 7;
    const int m0 = blockIdx.y * 128, n0 = blockIdx.x * 128;
    const float* A = ((z < 8) ? A0 : A1) + (size_t)m0 * DIM;
    const float* X = ((z < 8) ? X0 : X1) + (size_t)b * DIM * YD;
    float*       C = ((z < 8) ? C0 : C1) + (size_t)b * INNER * YD;

    const int k2 = t >> 4, nl0 = t & 15;
    float4 av[4]; float pa[8], pb[8];

    pref_rows(A, DIM, t, av);
    {
        const float* xr0 = &X[(size_t)(2 * k2) * YD + n0];
        const float* xr1 = xr0 + YD;
#pragma unroll
        for (int j = 0; j < 8; j++) { pa[j] = xr0[nl0 + 16 * j]; pb[j] = xr1[nl0 + 16 * j]; }
    }
    commit_rows(smg, smg + ABUF, t, av);
#pragma unroll
    for (int j = 0; j < 8; j++) {
        uint32_t h, l; cvt_pair(pa[j], pb[j], h, l);
        int nl = nl0 + 16 * j;
        *(uint32_t*)(smg + 2 * ABUF + nl * (SROW * 2) + k2 * 4) = h;
        *(uint32_t*)(smg + 3 * ABUF + nl * (SROW * 2) + k2 * 4) = l;
    }
    __syncthreads();

    for (int c = 0; c < 8; c++) {
        if (c < 7) {
            int k0 = (c + 1) * 32;
            pref_rows(A + k0, DIM, t, av);
            const float* xr0 = &X[(size_t)(k0 + 2 * k2) * YD + n0];
            const float* xr1 = xr0 + YD;
#pragma unroll
            for (int j = 0; j < 8; j++) { pa[j] = xr0[nl0 + 16 * j]; pb[j] = xr1[nl0 + 16 * j]; }
        }
        mma_chunk2(sbase + (c & 1) * STAGE, acc, lane, wm, wn);
        if (c < 7) {
            char* st = smg + ((c + 1) & 1) * STAGE;
            commit_rows(st, st + ABUF, t, av);
#pragma unroll
            for (int j = 0; j < 8; j++) {
                uint32_t h, l; cvt_pair(pa[j], pb[j], h, l);
                int nl = nl0 + 16 * j;
                *(uint32_t*)(st + 2 * ABUF + nl * (SROW * 2) + k2 * 4) = h;
                *(uint32_t*)(st + 3 * ABUF + nl * (SROW * 2) + k2 * 4) = l;
            }
        }
        __syncthreads();
    }
    store_c(C, YD, m0, n0, acc, lane, wm, wn);
}

// =====================================================================
// KV projection, split-K x2. grid(4, 8, 16), 256 thr, 64 chunks each.
// =====================================================================
__global__ __launch_bounds__(256, 2) void kvproj_tc(
    const float* __restrict__ W0, const float* __restrict__ X0,
    float* __restrict__ C0, float* __restrict__ P0,
    const float* __restrict__ W1, const float* __restrict__ X1,
    float* __restrict__ C1, float* __restrict__ P1)
{
    GEMM_PROLOG
    const int z = blockIdx.z, b = z & 7;
    const int wsel = blockIdx.x & 1, ksel = blockIdx.x >> 1;
    const int m0 = blockIdx.y * 128, w0 = wsel * 128;
    const int K = DIM * 16;
    const float* A  = ((z < 8) ? W0 : W1) + (size_t)m0 * K;
    const float* xp = ((z < 8) ? X0 : X1) + (size_t)b * DIM * YD;
    float* C = ((z < 8) ? (ksel ? P0 : C0) : (ksel ? P1 : C1)) + (size_t)b * 2 * INNER * WW;
    const int gbase = ksel * 64;

    const int p = t >> 7, wl = t & 127;
    float4 av[4], bv[4];

    pref_rows(A + (size_t)gbase * 32, K, t, av);
    {
        const float4* src = (const float4*)(xp + (size_t)(2 * gbase + p) * YD + (size_t)(w0 + wl) * 16);
        bv[0] = src[0]; bv[1] = src[1]; bv[2] = src[2]; bv[3] = src[3];
    }
    commit_rows(smg, smg + ABUF, t, av);
    {
        uint32_t h[8], l[8];
        cvt_pair(bv[0].x, bv[0].y, h[0], l[0]); cvt_pair(bv[0].z, bv[0].w, h[1], l[1]);
        cvt_pair(bv[1].x, bv[1].y, h[2], l[2]); cvt_pair(bv[1].z, bv[1].w, h[3], l[3]);
        cvt_pair(bv[2].x, bv[2].y, h[4], l[4]); cvt_pair(bv[2].z, bv[2].w, h[5], l[5]);
        cvt_pair(bv[3].x, bv[3].y, h[6], l[6]); cvt_pair(bv[3].z, bv[3].w, h[7], l[7]);
        char* dh = smg + 2 * ABUF + wl * (SROW * 2) + p * 32;
        char* dl = smg + 3 * ABUF + wl * (SROW * 2) + p * 32;
        *(uint4*)dh       = make_uint4(h[0], h[1], h[2], h[3]);
        *((uint4*)dh + 1) = make_uint4(h[4], h[5], h[6], h[7]);
        *(uint4*)dl       = make_uint4(l[0], l[1], l[2], l[3]);
        *((uint4*)dl + 1) = make_uint4(l[4], l[5], l[6], l[7]);
    }
    __syncthreads();

    for (int c = 0; c < 64; c++) {
        if (c < 63) {
            int g = gbase + c + 1;
            pref_rows(A + (size_t)g * 32, K, t, av);
            const float4* src = (const float4*)(xp + (size_t)(2 * g + p) * YD + (size_t)(w0 + wl) * 16);
            bv[0] = src[0]; bv[1] = src[1]; bv[2] = src[2]; bv[3] = src[3];
        }
        mma_chunk2(sbase + (c & 1) * STAGE, acc, lane, wm, wn);
        if (c < 63) {
            char* st = smg + ((c + 1) & 1) * STAGE;
            commit_rows(st, st + ABUF, t, av);
            uint32_t h[8], l[8];
            cvt_pair(bv[0].x, bv[0].y, h[0], l[0]); cvt_pair(bv[0].z, bv[0].w, h[1], l[1]);
            cvt_pair(bv[1].x, bv[1].y, h[2], l[2]); cvt_pair(bv[1].z, bv[1].w, h[3], l[3]);
            cvt_pair(bv[2].x, bv[2].y, h[4], l[4]); cvt_pair(bv[2].z, bv[2].w, h[5], l[5]);
            cvt_pair(bv[3].x, bv[3].y, h[6], l[6]); cvt_pair(bv[3].z, bv[3].w, h[7], l[7]);
            char* dh = st + 2 * ABUF + wl * (SROW * 2) + p * 32;
            char* dl = st + 3 * ABUF + wl * (SROW * 2) + p * 32;
            *(uint4*)dh       = make_uint4(h[0], h[1], h[2], h[3]);
            *((uint4*)dh + 1) = make_uint4(h[4], h[5], h[6], h[7]);
            *(uint4*)dl       = make_uint4(l[0], l[1], l[2], l[3]);
            *((uint4*)dl + 1) = make_uint4(l[4], l[5], l[6], l[7]);
        }
        __syncthreads();
    }
    store_c(C, WW, m0, w0, acc, lane, wm, wn);
}

__global__ __launch_bounds__(256) void kv_reduce(
    float* __restrict__ a, const float* __restrict__ pa,
    float* __restrict__ b, const float* __restrict__ pb)
{
    size_t i = ((size_t)blockIdx.x * 256 + threadIdx.x) * 4;
    float4 v0 = *(float4*)&a[i], q0 = *(const float4*)&pa[i];
    v0.x += q0.x; v0.y += q0.y; v0.z += q0.z; v0.w += q0.w;
    *(float4*)&a[i] = v0;
    float4 v1 = *(float4*)&b[i], q1 = *(const float4*)&pb[i];
    v1.x += q1.x; v1.y += q1.y; v1.z += q1.z; v1.w += q1.w;
    *(float4*)&b[i] = v1;
}

// =====================================================================
// Attention (round-6 form). CTA = 128 q rows x (b,h,stream); 8 warps.
// =====================================================================
#define QROW_B 144      // 72 bf16 per row
#define VROW_B 528      // 264 bf16 per row
#define ATTN_SMEM 178176

__global__ __launch_bounds__(256, 1) void attn_tc(
    const float* __restrict__ Q0, const float* __restrict__ KVa, float* __restrict__ O0,
    const float* __restrict__ Q1, const float* __restrict__ KVb, float* __restrict__ O1)
{
    extern __shared__ char sm[];
    const int z = blockIdx.z, b = z & 7;
    const float* Q  = (z < NB) ? Q0 : Q1;
    const float* KV = (z < NB) ? KVa : KVb;
    float*       O  = (z < NB) ? O0 : O1;
    const int h  = blockIdx.y;
    const int i0 = blockIdx.x * 128;

    char* sQh = sm;            char* sQl = sm + 18432;
    char* sKh = sm + 36864;    char* sKl = sm + 73728;
    char* sVh = sm + 110592;   char* sVl = sm + 144384;

    const int t = threadIdx.x, lane = t & 31, wid = t >> 5;

    const float* Qb = Q + ((size_t)b * INNER + h * 64) * YD + i0;
    const float* Kb = KV + ((size_t)b * 1024 + h * 64) * WW;
    const float* Vb = KV + ((size_t)b * 1024 + 512 + h * 64) * WW;

#pragma unroll
    for (int u = 0; u < 16; u++) {
        int idx = u * 256 + t;
        int d2 = idx >> 7, i = idx & 127;
        float a = Qb[(size_t)(2 * d2) * YD + i];
        float c = Qb[(size_t)(2 * d2 + 1) * YD + i];
        uint32_t hh, ll; cvt_pair(a, c, hh, ll);
        *(uint32_t*)(sQh + i * QROW_B + d2 * 4) = hh;
        *(uint32_t*)(sQl + i * QROW_B + d2 * 4) = ll;
    }
#pragma unroll
    for (int u = 0; u < 32; u++) {
        int idx = u * 256 + t;
        int d2 = idx >> 8, j = idx & 255;
        float a = Kb[(size_t)(2 * d2) * WW + j];
        float c = Kb[(size_t)(2 * d2 + 1) * WW + j];
        uint32_t hh, ll; cvt_pair(a, c, hh, ll);
        *(uint32_t*)(sKh + j * QROW_B + d2 * 4) = hh;
        *(uint32_t*)(sKl + j * QROW_B + d2 * 4) = ll;
    }
#pragma unroll
    for (int u = 0; u < 16; u++) {
        int idx = u * 256 + t;
        int d = idx >> 6, j4 = (idx & 63) * 4;
        float4 f = *(const float4*)&Vb[(size_t)d * WW + j4];
        uint32_t h0, l0, h1, l1;
        cvt_pair(f.x, f.y, h0, l0); cvt_pair(f.z, f.w, h1, l1);
        *(uint2*)(sVh + d * VROW_B + j4 * 2) = make_uint2(h0, h1);
        *(uint2*)(sVl + d * VROW_B + j4 * 2) = make_uint2(l0, l1);
    }
    __syncthreads();

    const uint32_t uQh = smem_u32(sQh), uQl = smem_u32(sQl);
    const uint32_t uKh = smem_u32(sKh), uKl = smem_u32(sKl);
    const uint32_t uVh = smem_u32(sVh), uVl = smem_u32(sVl);

    const int arow  = lane & 15, acol8 = (lane >> 4) * 8;
    const int brow  = ((lane >> 4) & 1) * 8 + (lane & 7);
    const int bcol8 = ((lane >> 3) & 1) * 8;

    float s[32][4];
#pragma unroll
    for (int nt = 0; nt < 32; nt++)
#pragma unroll
        for (int q = 0; q < 4; q++) s[nt][q] = 0.f;

#pragma unroll
    for (int kc = 0; kc < 4; kc++) {
        uint32_t ah[4], al[4];
        uint32_t aoff = (uint32_t)(wid * 16 + arow) * QROW_B + (kc * 16 + acol8) * 2;
        LDSM_X4(ah[0], ah[1], ah[2], ah[3], uQh + aoff);
        LDSM_X4(al[0], al[1], al[2], al[3], uQl + aoff);
#pragma unroll
        for (int np = 0; np < 16; np++) {
            uint32_t boff = (uint32_t)(np * 16 + brow) * QROW_B + (kc * 16 + bcol8) * 2;
            uint32_t bh[4], bl[4];
            LDSM_X4(bh[0], bh[1], bh[2], bh[3], uKh + boff);
            LDSM_X4(bl[0], bl[1], bl[2], bl[3], uKl + boff);
            mma_bf16(s[2*np],   ah, &bh[0]);
            mma_bf16(s[2*np],   ah, &bl[0]);
            mma_bf16(s[2*np],   al, &bh[0]);
            mma_bf16(s[2*np+1], ah, &bh[2]);
            mma_bf16(s[2*np+1], ah, &bl[2]);
            mma_bf16(s[2*np+1], al, &bh[2]);
        }
    }

    float mx1 = -1e30f, mx2 = -1e30f;
#pragma unroll
    for (int nt = 0; nt < 32; nt++) {
        s[nt][0] *= ASCALE; s[nt][1] *= ASCALE;
        s[nt][2] *= ASCALE; s[nt][3] *= ASCALE;
        mx1 = fmaxf(mx1, fmaxf(s[nt][0], s[nt][1]));
        mx2 = fmaxf(mx2, fmaxf(s[nt][2], s[nt][3]));
    }
    mx1 = fmaxf(mx1, __shfl_xor_sync(0xffffffffu, mx1, 1));
    mx1 = fmaxf(mx1, __shfl_xor_sync(0xffffffffu, mx1, 2));
    mx2 = fmaxf(mx2, __shfl_xor_sync(0xffffffffu, mx2, 1));
    mx2 = fmaxf(mx2, __shfl_xor_sync(0xffffffffu, mx2, 2));
    float sum1 = 0.f, sum2 = 0.f;
#pragma unroll
    for (int nt = 0; nt < 32; nt++) {
        s[nt][0] = __expf(s[nt][0] - mx1); sum1 += s[nt][0];
        s[nt][1] = __expf(s[nt][1] - mx1); sum1 += s[nt][1];
        s[nt][2] = __expf(s[nt][2] - mx2); sum2 += s[nt][2];
        s[nt][3] = __expf(s[nt][3] - mx2); sum2 += s[nt][3];
    }
    sum1 += __shfl_xor_sync(0xffffffffu, sum1, 1);
    sum1 += __shfl_xor_sync(0xffffffffu, sum1, 2);
    sum2 += __shfl_xor_sync(0xffffffffu, sum2, 1);
    sum2 += __shfl_xor_sync(0xffffffffu, sum2, 2);
    const float i1 = 1.f / sum1, i2 = 1.f / sum2;

    float o[8][4];
#pragma unroll
    for (int dt = 0; dt < 8; dt++)
#pragma unroll
        for (int q = 0; q < 4; q++) o[dt][q] = 0.f;

#pragma unroll
    for (int kc = 0; kc < 16; kc++) {
        uint32_t ph[4], pl[4];
        cvt_pair(s[2*kc][0]   * i1, s[2*kc][1]   * i1, ph[0], pl[0]);
        cvt_pair(s[2*kc][2]   * i2, s[2*kc][3]   * i2, ph[1], pl[1]);
        cvt_pair(s[2*kc+1][0] * i1, s[2*kc+1][1] * i1, ph[2], pl[2]);
        cvt_pair(s[2*kc+1][2] * i2, s[2*kc+1][3] * i2, ph[3], pl[3]);
#pragma unroll
        for (int dp = 0; dp < 4; dp++) {
            uint32_t voff = (uint32_t)(dp * 16 + brow) * VROW_B + (kc * 16 + bcol8) * 2;
            uint32_t vh[4], vl[4];
            LDSM_X4(vh[0], vh[1], vh[2], vh[3], uVh + voff);
            LDSM_X4(vl[0], vl[1], vl[2], vl[3], uVl + voff);
            mma_bf16(o[2*dp],   ph, &vh[0]);
            mma_bf16(o[2*dp],   pl, &vh[0]);
            mma_bf16(o[2*dp],   ph, &vl[0]);
            mma_bf16(o[2*dp+1], ph, &vh[2]);
            mma_bf16(o[2*dp+1], pl, &vh[2]);
            mma_bf16(o[2*dp+1], ph, &vl[2]);
        }
    }

    const int g = lane >> 2, tt = lane & 3;
    const int y = i0 + wid * 16 + g;
    size_t rb = ((size_t)b * YD + y) * INNER + h * 64;
#pragma unroll
    for (int dt = 0; dt < 8; dt++) {
        *(float2*)&O[rb + dt * 8 + 2 * tt] = make_float2(o[dt][0], o[dt][1]);
        *(float2*)&O[rb + (size_t)8 * INNER + dt * 8 + 2 * tt] = make_float2(o[dt][2], o[dt][3]);
    }
}

// =====================================================================
// Out projection (NT, both phases) + residual fuse. grid(32,2,8), 32 chunks.
// =====================================================================
__global__ __launch_bounds__(256, 2) void outproj_tc(
    const float* __restrict__ W0, const float* __restrict__ O0,
    const float* __restrict__ W1, const float* __restrict__ O1,
    const float* __restrict__ b0, const float* __restrict__ b1,
    const float* __restrict__ x0, const float* __restrict__ x1,
    float* __restrict__ out)
{
    GEMM_PROLOG
    const int b = blockIdx.z;
    const int m0 = blockIdx.y * 128, n0 = blockIdx.x * 128;

    float4 av[4], bv[4];
    const float* Wp[2] = { W0 + (size_t)m0 * INNER, W1 + (size_t)m0 * INNER };
    const float* Op[2] = { O0 + ((size_t)b * YD + n0) * INNER,
                           O1 + ((size_t)b * YD + n0) * INNER };

    pref_rows(Wp[0], INNER, t, av);
    pref_rows(Op[0], INNER, t, bv);
    commit_rows(smg, smg + ABUF, t, av);
    commit_rows(smg + 2 * ABUF, smg + 3 * ABUF, t, bv);
    __syncthreads();

    for (int c = 0; c < 32; c++) {
        if (c < 31) {
            int cn = c + 1;
            int phs = cn >> 4, k0 = (cn & 15) * 32;
            pref_rows(Wp[phs] + k0, INNER, t, av);
            pref_rows(Op[phs] + k0, INNER, t, bv);
        }
        mma_chunk2(sbase + (c & 1) * STAGE, acc, lane, wm, wn);
        if (c < 31) {
            char* st = smg + ((c + 1) & 1) * STAGE;
            commit_rows(st, st + ABUF, t, av);
            commit_rows(st + 2 * ABUF, st + 3 * ABUF, t, bv);
        }
        __syncthreads();
    }

    const int g = lane >> 2, tt = lane & 3;
#pragma unroll
    for (int mt = 0; mt < 4; mt++) {
        int r = m0 + wm + mt * 16 + g;
        float biasA = 0.5f * (b0[r] + b1[r]);
        float biasB = 0.5f * (b0[r + 8] + b1[r + 8]);
#pragma unroll
        for (int nt = 0; nt < 4; nt++) {
            int cc = n0 + wn + nt * 8 + 2 * tt;
            size_t iA = ((size_t)b * DIM + r) * YD + cc;
            size_t iB = ((size_t)b * DIM + r + 8) * YD + cc;
            float2 xa = *(const float2*)&x0[iA], xb = *(const float2*)&x1[iA];
            float2 oo;
            oo.x = 0.5f * (acc[mt][nt][0] + xa.x + xb.x) + biasA;
            oo.y = 0.5f * (acc[mt][nt][1] + xa.y + xb.y) + biasA;
            *(float2*)&out[iA] = oo;
            xa = *(const float2*)&x0[iB]; xb = *(const float2*)&x1[iB];
            oo.x = 0.5f * (acc[mt][nt][2] + xa.x + xb.x) + biasB;
            oo.y = 0.5f * (acc[mt][nt][3] + xa.y + xb.y) + biasB;
            *(float2*)&out[iB] = oo;
        }
    }
}

// =====================================================================
extern "C" void kernel_launch(void* const* d_in, const int* in_sizes, int n_in,
                              void* d_out, int out_size)
{
    const float* x0    = (const float*)d_in[0];
    const float* x1    = (const float*)d_in[1];
    const float* Wq0   = (const float*)d_in[2];
    const float* Wkv0  = (const float*)d_in[3];
    const float* Wq1   = (const float*)d_in[4];
    const float* Wkv1  = (const float*)d_in[5];
    const float* Wout0 = (const float*)d_in[6];
    const float* bout0 = (const float*)d_in[7];
    const float* Wout1 = (const float*)d_in[8];
    const float* bout1 = (const float*)d_in[9];
    float* out = (float*)d_out;

    float *Q0, *Q1, *KV0, *KV1, *KVp0, *KVp1, *O0, *O1;
    cudaGetSymbolAddress((void**)&Q0,   g_Q0);
    cudaGetSymbolAddress((void**)&Q1,   g_Q1);
    cudaGetSymbolAddress((void**)&KV0,  g_KV0);
    cudaGetSymbolAddress((void**)&KV1,  g_KV1);
    cudaGetSymbolAddress((void**)&KVp0, g_KVp0);
    cudaGetSymbolAddress((void**)&KVp1, g_KVp1);
    cudaGetSymbolAddress((void**)&O0,   g_O0);
    cudaGetSymbolAddress((void**)&O1,   g_O1);

    cudaFuncSetAttribute(qproj_tc,   cudaFuncAttributeMaxDynamicSharedMemorySize, GEMM_DSMEM);
    cudaFuncSetAttribute(kvproj_tc,  cudaFuncAttributeMaxDynamicSharedMemorySize, GEMM_DSMEM);
    cudaFuncSetAttribute(outproj_tc, cudaFuncAttributeMaxDynamicSharedMemorySize, GEMM_DSMEM);
    cudaFuncSetAttribute(attn_tc,    cudaFuncAttributeMaxDynamicSharedMemorySize, ATTN_SMEM);

    qproj_tc<<<dim3(YD / 128, INNER / 128, 2 * NB), 256, GEMM_DSMEM>>>(
        Wq0, x0, Q0, Wq1, x1, Q1);
    kvproj_tc<<<dim3(4, (2 * INNER) / 128, 2 * NB), 256, GEMM_DSMEM>>>(
        Wkv0, x0, KV0, KVp0, Wkv1, x1, KV1, KVp1);
    kv_reduce<<<dim3((NB * 2 * INNER * WW) / (256 * 4)), 256>>>(KV0, KVp0, KV1, KVp1);
    attn_tc<<<dim3(YD / 128, HH, 2 * NB), 256, ATTN_SMEM>>>(
        Q0, KV1, O0, Q1, KV0, O1);
    outproj_tc<<<dim3(YD / 128, DIM / 128, NB), 256, GEMM_DSMEM>>>(
        Wout0, O0, Wout1, O1, bout0, bout1, x0, x1, out);
}

// round 9
// speedup vs baseline: 1.1148x; 1.0939x over previous
#include <cuda_runtime.h>
#include <math.h>
#include <cstdint>

#define NB    8
#define DIM   256
#define YD    4096
#define HH    8
#define INNER 512
#define WW    256
#define ASCALE 0.125f

// ---------------- mma.sync / ldmatrix helpers (arch-agnostic, sm_80+) ------
__device__ __forceinline__ uint32_t smem_u32(const void* p) {
    uint32_t a;
    asm("{ .reg .u64 tmp; cvta.to.shared.u64 tmp, %1; cvt.u32.u64 %0, tmp; }"
        : "=r"(a) : "l"(p));
    return a;
}
#define LDSM_X4(r0, r1, r2, r3, addr) \
    asm volatile("ldmatrix.sync.aligned.m8n8.x4.shared.b16 {%0,%1,%2,%3}, [%4];" \
        : "=r"(r0), "=r"(r1), "=r"(r2), "=r"(r3) : "r"(addr))

__device__ __forceinline__ void mma_bf16(float c[4], const uint32_t a[4], const uint32_t b[2]) {
    asm volatile("mma.sync.aligned.m16n8k16.row.col.f32.bf16.bf16.f32 "
        "{%0,%1,%2,%3}, {%4,%5,%6,%7}, {%8,%9}, {%0,%1,%2,%3};"
        : "+f"(c[0]), "+f"(c[1]), "+f"(c[2]), "+f"(c[3])
        : "r"(a[0]), "r"(a[1]), "r"(a[2]), "r"(a[3]), "r"(b[0]), "r"(b[1]));
}

// split fp32 pair -> hi (truncated bf16) pair + lo (bf16 of residual) pair.
__device__ __forceinline__ void cvt_pair(float a, float b, uint32_t& hi2, uint32_t& lo2) {
    uint32_t ua = __float_as_uint(a), ub = __float_as_uint(b);
    hi2 = __byte_perm(ua, ub, 0x7632);
    float ra = a - __uint_as_float(ua & 0xffff0000u);
    float rb = b - __uint_as_float(ub & 0xffff0000u);
    asm("cvt.rn.bf16x2.f32 %0, %1, %2;" : "=r"(lo2) : "f"(rb), "f"(ra));
}

// ---------------- scratch ----------------
__device__ float g_Q0[NB * INNER * YD];
__device__ float g_Q1[NB * INNER * YD];
__device__ float g_KV0[NB * 2 * INNER * WW];
__device__ float g_KV1[NB * 2 * INNER * WW];
__device__ float g_O0[(size_t)NB * YD * INNER];
__device__ float g_O1[(size_t)NB * YD * INNER];

// GEMM SMEM tile: 128 rows x 32 bf16, padded to 40 (80 B = 5x16B)
#define SROW 40

__device__ __forceinline__ void load_rows32(
    const float* __restrict__ src, size_t ld,
    uint16_t* hiB, uint16_t* loB, int t)
{
    int row = t >> 1, ks = (t & 1) * 16;
    const float4* p = (const float4*)(src + (size_t)row * ld + ks);
    float4 f0 = p[0], f1 = p[1], f2 = p[2], f3 = p[3];
    uint32_t h[8], l[8];
    cvt_pair(f0.x, f0.y, h[0], l[0]); cvt_pair(f0.z, f0.w, h[1], l[1]);
    cvt_pair(f1.x, f1.y, h[2], l[2]); cvt_pair(f1.z, f1.w, h[3], l[3]);
    cvt_pair(f2.x, f2.y, h[4], l[4]); cvt_pair(f2.z, f2.w, h[5], l[5]);
    cvt_pair(f3.x, f3.y, h[6], l[6]); cvt_pair(f3.z, f3.w, h[7], l[7]);
    char* dh = (char*)hiB + row * (SROW * 2) + ks * 2;
    char* dl = (char*)loB + row * (SROW * 2) + ks * 2;
    *(uint4*)dh       = make_uint4(h[0], h[1], h[2], h[3]);
    *((uint4*)dh + 1) = make_uint4(h[4], h[5], h[6], h[7]);
    *(uint4*)dl       = make_uint4(l[0], l[1], l[2], l[3]);
    *((uint4*)dl + 1) = make_uint4(l[4], l[5], l[6], l[7]);
}

__device__ __forceinline__ void mma_chunk(
    uint32_t aHi, uint32_t aLo, uint32_t bHi, uint32_t bLo,
    float acc[4][4][4], int lane, int wm, int wn)
{
    const int arow  = lane & 15;
    const int acol8 = (lane >> 4) * 8;
    const int brow  = ((lane >> 4) & 1) * 8 + (lane & 7);
    const int bcol8 = ((lane >> 3) & 1) * 8;
#pragma unroll
    for (int ks = 0; ks < 32; ks += 16) {
        uint32_t ah[4][4], al[4][4], bh[4][2], bl[4][2];
#pragma unroll
        for (int mt = 0; mt < 4; mt++) {
            uint32_t off = (uint32_t)(wm + mt * 16 + arow) * (SROW * 2) + (ks + acol8) * 2;
            LDSM_X4(ah[mt][0], ah[mt][1], ah[mt][2], ah[mt][3], aHi + off);
            LDSM_X4(al[mt][0], al[mt][1], al[mt][2], al[mt][3], aLo + off);
        }
#pragma unroll
        for (int np = 0; np < 2; np++) {
            uint32_t off = (uint32_t)(wn + np * 16 + brow) * (SROW * 2) + (ks + bcol8) * 2;
            LDSM_X4(bh[np*2][0], bh[np*2][1], bh[np*2+1][0], bh[np*2+1][1], bHi + off);
            LDSM_X4(bl[np*2][0], bl[np*2][1], bl[np*2+1][0], bl[np*2+1][1], bLo + off);
        }
#pragma unroll
        for (int mt = 0; mt < 4; mt++)
#pragma unroll
            for (int nt = 0; nt < 4; nt++) {
                mma_bf16(acc[mt][nt], ah[mt], bh[nt]);
                mma_bf16(acc[mt][nt], ah[mt], bl[nt]);
                mma_bf16(acc[mt][nt], al[mt], bh[nt]);
            }
    }
}

__device__ __forceinline__ void store_c(
    float* C, size_t ldc, int m0, int n0,
    float acc[4][4][4], int lane, int wm, int wn)
{
    int g = lane >> 2, tt = lane & 3;
#pragma unroll
    for (int mt = 0; mt < 4; mt++) {
        int r = m0 + wm + mt * 16 + g;
#pragma unroll
        for (int nt = 0; nt < 4; nt++) {
            int cc = n0 + wn + nt * 8 + 2 * tt;
            *(float2*)&C[(size_t)r * ldc + cc]       = make_float2(acc[mt][nt][0], acc[mt][nt][1]);
            *(float2*)&C[(size_t)(r + 8) * ldc + cc] = make_float2(acc[mt][nt][2], acc[mt][nt][3]);
        }
    }
}

#define GEMM_PROLOG \
    __shared__ __align__(16) uint16_t sAhi[128 * SROW], sAlo[128 * SROW]; \
    __shared__ __align__(16) uint16_t sBhi[128 * SROW], sBlo[128 * SROW]; \
    const int t = threadIdx.x, lane = t & 31, wid = t >> 5; \
    const int wm = (wid & 1) * 64, wn = (wid >> 1) * 32; \
    const uint32_t aHi = smem_u32(sAhi), aLo = smem_u32(sAlo); \
    const uint32_t bHi = smem_u32(sBhi), bLo = smem_u32(sBlo); \
    float acc[4][4][4]; \
    _Pragma("unroll") for (int i = 0; i < 4; i++) \
    _Pragma("unroll") for (int j = 0; j < 4; j++) \
    _Pragma("unroll") for (int q = 0; q < 4; q++) acc[i][j][q] = 0.f;

// =====================================================================
// Q projection (round-6 form). M=512,K=256,N=4096. grid(32,4,16), 256 thr.
// =====================================================================
__global__ __launch_bounds__(256) void qproj_tc(
    const float* __restrict__ A0, const float* __restrict__ X0, float* __restrict__ C0,
    const float* __restrict__ A1, const float* __restrict__ X1, float* __restrict__ C1)
{
    GEMM_PROLOG
    const int z = blockIdx.z, b = z & 7;
    const int m0 = blockIdx.y * 128, n0 = blockIdx.x * 128;
    const float* A = ((z < 8) ? A0 : A1) + (size_t)m0 * DIM;
    const float* X = ((z < 8) ? X0 : X1) + (size_t)b * DIM * YD;
    float*       C = ((z < 8) ? C0 : C1) + (size_t)b * INNER * YD;

    const int k2 = t >> 4, nl0 = t & 15;
    for (int c = 0; c < 8; c++) {
        const int k0 = c * 32;
        if (c) __syncthreads();
        load_rows32(A + k0, DIM, sAhi, sAlo, t);
        {
            const float* xr0 = &X[(size_t)(k0 + 2 * k2) * YD + n0];
            const float* xr1 = xr0 + YD;
#pragma unroll
            for (int j = 0; j < 8; j++) {
                int nl = nl0 + 16 * j;
                uint32_t h, l;
                cvt_pair(xr0[nl], xr1[nl], h, l);
                *(uint32_t*)((char*)sBhi + nl * (SROW * 2) + k2 * 4) = h;
                *(uint32_t*)((char*)sBlo + nl * (SROW * 2) + k2 * 4) = l;
            }
        }
        __syncthreads();
        mma_chunk(aHi, aLo, bHi, bLo, acc, lane, wm, wn);
    }
    store_c(C, YD, m0, n0, acc, lane, wm, wn);
}

// =====================================================================
// KV projection (round-6 form). M=1024,K=4096,N(w)=256. grid(2,8,16).
// =====================================================================
__global__ __launch_bounds__(256) void kvproj_tc(
    const float* __restrict__ W0, const float* __restrict__ X0, float* __restrict__ C0,
    const float* __restrict__ W1, const float* __restrict__ X1, float* __restrict__ C1)
{
    GEMM_PROLOG
    const int z = blockIdx.z, b = z & 7;
    const int m0 = blockIdx.y * 128, w0 = blockIdx.x * 128;
    const int K = DIM * 16;
    const float* A  = ((z < 8) ? W0 : W1) + (size_t)m0 * K;
    const float* xp = ((z < 8) ? X0 : X1) + (size_t)b * DIM * YD;
    float*       C  = ((z < 8) ? C0 : C1) + (size_t)b * 2 * INNER * WW;

    const int p = t >> 7, wl = t & 127;
    for (int c = 0; c < 128; c++) {
        if (c) __syncthreads();
        load_rows32(A + c * 32, K, sAhi, sAlo, t);
        {
            const float4* src = (const float4*)(xp + (size_t)(2 * c + p) * YD + (size_t)(w0 + wl) * 16);
            float4 f0 = src[0], f1 = src[1], f2 = src[2], f3 = src[3];
            uint32_t h[8], l[8];
            cvt_pair(f0.x, f0.y, h[0], l[0]); cvt_pair(f0.z, f0.w, h[1], l[1]);
            cvt_pair(f1.x, f1.y, h[2], l[2]); cvt_pair(f1.z, f1.w, h[3], l[3]);
            cvt_pair(f2.x, f2.y, h[4], l[4]); cvt_pair(f2.z, f2.w, h[5], l[5]);
            cvt_pair(f3.x, f3.y, h[6], l[6]); cvt_pair(f3.z, f3.w, h[7], l[7]);
            char* dh = (char*)sBhi + wl * (SROW * 2) + p * 32;
            char* dl = (char*)sBlo + wl * (SROW * 2) + p * 32;
            *(uint4*)dh       = make_uint4(h[0], h[1], h[2], h[3]);
            *((uint4*)dh + 1) = make_uint4(h[4], h[5], h[6], h[7]);
            *(uint4*)dl       = make_uint4(l[0], l[1], l[2], l[3]);
            *((uint4*)dl + 1) = make_uint4(l[4], l[5], l[6], l[7]);
        }
        __syncthreads();
        mma_chunk(aHi, aLo, bHi, bLo, acc, lane, wm, wn);
    }
    store_c(C, WW, m0, w0, acc, lane, wm, wn);
}

// =====================================================================
// Attention, chunked online softmax. CTA = 128 q rows; 8 warps x 16 rows.
// KV processed in 4 chunks of 64 tokens; Q resident; K/V chunk staged
// per iteration. 73728 B dynamic smem, <=128 regs -> 2 CTAs/SM.
// =====================================================================
#define QROW_B 144      // 72 bf16 per row (Q rows: d; K rows: d; V rows: j-chunk)
#define ATTN_DSMEM 73728

__global__ __launch_bounds__(256, 2) void attn_tc(
    const float* __restrict__ Q0, const float* __restrict__ KVa, float* __restrict__ O0,
    const float* __restrict__ Q1, const float* __restrict__ KVb, float* __restrict__ O1)
{
    extern __shared__ char sm[];
    const int z = blockIdx.z, b = z & 7;
    const float* Q  = (z < NB) ? Q0 : Q1;
    const float* KV = (z < NB) ? KVa : KVb;
    float*       O  = (z < NB) ? O0 : O1;
    const int h  = blockIdx.y;
    const int i0 = blockIdx.x * 128;

    char* sQh = sm;                  char* sQl = sm + 18432;
    char* sKh = sm + 36864;          char* sKl = sm + 36864 + 9216;
    char* sVh = sm + 36864 + 18432;  char* sVl = sm + 36864 + 27648;

    const int t = threadIdx.x, lane = t & 31, wid = t >> 5;

    const float* Qb = Q + ((size_t)b * INNER + h * 64) * YD + i0;
    const float* Kb = KV + ((size_t)b * 1024 + h * 64) * WW;
    const float* Vb = KV + ((size_t)b * 1024 + 512 + h * 64) * WW;

    // ---- stage Q [i][d] hi/lo (resident for whole CTA) ----
#pragma unroll
    for (int u = 0; u < 16; u++) {
        int idx = u * 256 + t;
        int d2 = idx >> 7, i = idx & 127;
        float a = Qb[(size_t)(2 * d2) * YD + i];
        float c = Qb[(size_t)(2 * d2 + 1) * YD + i];
        uint32_t hh, ll; cvt_pair(a, c, hh, ll);
        *(uint32_t*)(sQh + i * QROW_B + d2 * 4) = hh;
        *(uint32_t*)(sQl + i * QROW_B + d2 * 4) = ll;
    }

    const uint32_t uQh = smem_u32(sQh), uQl = smem_u32(sQl);
    const uint32_t uKh = smem_u32(sKh), uKl = smem_u32(sKl);
    const uint32_t uVh = smem_u32(sVh), uVl = smem_u32(sVl);

    const int arow  = lane & 15, acol8 = (lane >> 4) * 8;
    const int brow  = ((lane >> 4) & 1) * 8 + (lane & 7);
    const int bcol8 = ((lane >> 3) & 1) * 8;

    float m1 = -1e30f, m2 = -1e30f, sum1 = 0.f, sum2 = 0.f;
    float o[8][4];
#pragma unroll
    for (int dt = 0; dt < 8; dt++)
#pragma unroll
        for (int q = 0; q < 4; q++) o[dt][q] = 0.f;

    for (int c = 0; c < 4; c++) {
        const int j0 = c * 64;
        __syncthreads();   // prev chunk compute done (also publishes Q on c==0)
        // ---- stage K chunk [j][d] hi/lo ----
#pragma unroll
        for (int u = 0; u < 8; u++) {
            int idx = u * 256 + t;
            int d2 = idx >> 6, j = idx & 63;
            float a = Kb[(size_t)(2 * d2) * WW + j0 + j];
            float cc = Kb[(size_t)(2 * d2 + 1) * WW + j0 + j];
            uint32_t hh, ll; cvt_pair(a, cc, hh, ll);
            *(uint32_t*)(sKh + j * QROW_B + d2 * 4) = hh;
            *(uint32_t*)(sKl + j * QROW_B + d2 * 4) = ll;
        }
        // ---- stage V chunk [d][j] hi/lo ----
#pragma unroll
        for (int u = 0; u < 8; u++) {
            int idx = u * 256 + t;
            int d = idx >> 5, j2 = idx & 31;
            float2 f = *(const float2*)&Vb[(size_t)d * WW + j0 + 2 * j2];
            uint32_t hh, ll; cvt_pair(f.x, f.y, hh, ll);
            *(uint32_t*)(sVh + d * QROW_B + j2 * 4) = hh;
            *(uint32_t*)(sVl + d * QROW_B + j2 * 4) = ll;
        }
        __syncthreads();

        // ---- QK^T chunk: 16 x 64 per warp ----
        float s[8][4];
#pragma unroll
        for (int nt = 0; nt < 8; nt++)
#pragma unroll
            for (int q = 0; q < 4; q++) s[nt][q] = 0.f;

#pragma unroll
        for (int kc = 0; kc < 4; kc++) {
            uint32_t ah[4], al[4];
            uint32_t aoff = (uint32_t)(wid * 16 + arow) * QROW_B + (kc * 16 + acol8) * 2;
            LDSM_X4(ah[0], ah[1], ah[2], ah[3], uQh + aoff);
            LDSM_X4(al[0], al[1], al[2], al[3], uQl + aoff);
#pragma unroll
            for (int np = 0; np < 4; np++) {
                uint32_t boff = (uint32_t)(np * 16 + brow) * QROW_B + (kc * 16 + bcol8) * 2;
                uint32_t bh[4], bl[4];
                LDSM_X4(bh[0], bh[1], bh[2], bh[3], uKh + boff);
                LDSM_X4(bl[0], bl[1], bl[2], bl[3], uKl + boff);
                mma_bf16(s[2*np],   ah, &bh[0]);
                mma_bf16(s[2*np],   ah, &bl[0]);
                mma_bf16(s[2*np],   al, &bh[0]);
                mma_bf16(s[2*np+1], ah, &bh[2]);
                mma_bf16(s[2*np+1], ah, &bl[2]);
                mma_bf16(s[2*np+1], al, &bh[2]);
            }
        }

        // ---- online softmax update (rows g and g+8) ----
        float cm1 = -1e30f, cm2 = -1e30f;
#pragma unroll
        for (int nt = 0; nt < 8; nt++) {
            s[nt][0] *= ASCALE; s[nt][1] *= ASCALE;
            s[nt][2] *= ASCALE; s[nt][3] *= ASCALE;
            cm1 = fmaxf(cm1, fmaxf(s[nt][0], s[nt][1]));
            cm2 = fmaxf(cm2, fmaxf(s[nt][2], s[nt][3]));
        }
        cm1 = fmaxf(cm1, __shfl_xor_sync(0xffffffffu, cm1, 1));
        cm1 = fmaxf(cm1, __shfl_xor_sync(0xffffffffu, cm1, 2));
        cm2 = fmaxf(cm2, __shfl_xor_sync(0xffffffffu, cm2, 1));
        cm2 = fmaxf(cm2, __shfl_xor_sync(0xffffffffu, cm2, 2));
        float m1n = fmaxf(m1, cm1), m2n = fmaxf(m2, cm2);
        float sc1 = __expf(m1 - m1n), sc2 = __expf(m2 - m2n);
        m1 = m1n; m2 = m2n;
#pragma unroll
        for (int dt = 0; dt < 8; dt++) {
            o[dt][0] *= sc1; o[dt][1] *= sc1;
            o[dt][2] *= sc2; o[dt][3] *= sc2;
        }
        float ls1 = 0.f, ls2 = 0.f;
#pragma unroll
        for (int nt = 0; nt < 8; nt++) {
            s[nt][0] = __expf(s[nt][0] - m1); ls1 += s[nt][0];
            s[nt][1] = __expf(s[nt][1] - m1); ls1 += s[nt][1];
            s[nt][2] = __expf(s[nt][2] - m2); ls2 += s[nt][2];
            s[nt][3] = __expf(s[nt][3] - m2); ls2 += s[nt][3];
        }
        sum1 = sum1 * sc1 + ls1;
        sum2 = sum2 * sc2 + ls2;

        // ---- P @ V chunk (unnormalized P as A fragments) ----
#pragma unroll
        for (int kk = 0; kk < 4; kk++) {
            uint32_t ph[4], pl[4];
            cvt_pair(s[2*kk][0],   s[2*kk][1],   ph[0], pl[0]);
            cvt_pair(s[2*kk][2],   s[2*kk][3],   ph[1], pl[1]);
            cvt_pair(s[2*kk+1][0], s[2*kk+1][1], ph[2], pl[2]);
            cvt_pair(s[2*kk+1][2], s[2*kk+1][3], ph[3], pl[3]);
#pragma unroll
            for (int dp = 0; dp < 4; dp++) {
                uint32_t voff = (uint32_t)(dp * 16 + brow) * QROW_B + (kk * 16 + bcol8) * 2;
                uint32_t vh[4], vl[4];
                LDSM_X4(vh[0], vh[1], vh[2], vh[3], uVh + voff);
                LDSM_X4(vl[0], vl[1], vl[2], vl[3], uVl + voff);
                mma_bf16(o[2*dp],   ph, &vh[0]);
                mma_bf16(o[2*dp],   pl, &vh[0]);
                mma_bf16(o[2*dp],   ph, &vl[0]);
                mma_bf16(o[2*dp+1], ph, &vh[2]);
                mma_bf16(o[2*dp+1], pl, &vh[2]);
                mma_bf16(o[2*dp+1], ph, &vl[2]);
            }
        }
    }

    // ---- finalize: combine quad partial sums, normalize, write ----
    sum1 += __shfl_xor_sync(0xffffffffu, sum1, 1);
    sum1 += __shfl_xor_sync(0xffffffffu, sum1, 2);
    sum2 += __shfl_xor_sync(0xffffffffu, sum2, 1);
    sum2 += __shfl_xor_sync(0xffffffffu, sum2, 2);
    const float i1 = 1.f / sum1, i2 = 1.f / sum2;

    const int g = lane >> 2, tt = lane & 3;
    const int y = i0 + wid * 16 + g;
    size_t rb = ((size_t)b * YD + y) * INNER + h * 64;
#pragma unroll
    for (int dt = 0; dt < 8; dt++) {
        *(float2*)&O[rb + dt * 8 + 2 * tt] =
            make_float2(o[dt][0] * i1, o[dt][1] * i1);
        *(float2*)&O[rb + (size_t)8 * INNER + dt * 8 + 2 * tt] =
            make_float2(o[dt][2] * i2, o[dt][3] * i2);
    }
}

// =====================================================================
// Out projection (round-6 form, NT, both phases) + residual fuse.
// =====================================================================
__global__ __launch_bounds__(256) void outproj_tc(
    const float* __restrict__ W0, const float* __restrict__ O0,
    const float* __restrict__ W1, const float* __restrict__ O1,
    const float* __restrict__ b0, const float* __restrict__ b1,
    const float* __restrict__ x0, const float* __restrict__ x1,
    float* __restrict__ out)
{
    GEMM_PROLOG
    const int b = blockIdx.z;
    const int m0 = blockIdx.y * 128, n0 = blockIdx.x * 128;

    for (int c = 0; c < 32; c++) {
        const int phs = c >> 4;
        const int k0  = (c & 15) * 32;
        const float* A  = ((phs == 0) ? W0 : W1) + (size_t)m0 * INNER;
        const float* Op = ((phs == 0) ? O0 : O1) + ((size_t)b * YD + n0) * INNER;
        if (c) __syncthreads();
        load_rows32(A + k0, INNER, sAhi, sAlo, t);
        load_rows32(Op + k0, INNER, sBhi, sBlo, t);
        __syncthreads();
        mma_chunk(aHi, aLo, bHi, bLo, acc, lane, wm, wn);
    }

    const int g = lane >> 2, tt = lane & 3;
#pragma unroll
    for (int mt = 0; mt < 4; mt++) {
        int r = m0 + wm + mt * 16 + g;
        float biasA = 0.5f * (b0[r] + b1[r]);
        float biasB = 0.5f * (b0[r + 8] + b1[r + 8]);
#pragma unroll
        for (int nt = 0; nt < 4; nt++) {
            int cc = n0 + wn + nt * 8 + 2 * tt;
            size_t iA = ((size_t)b * DIM + r) * YD + cc;
            size_t iB = ((size_t)b * DIM + r + 8) * YD + cc;
            float2 xa = *(const float2*)&x0[iA], xb = *(const float2*)&x1[iA];
            float2 oo;
            oo.x = 0.5f * (acc[mt][nt][0] + xa.x + xb.x) + biasA;
            oo.y = 0.5f * (acc[mt][nt][1] + xa.y + xb.y) + biasA;
            *(float2*)&out[iA] = oo;
            xa = *(const float2*)&x0[iB]; xb = *(const float2*)&x1[iB];
            oo.x = 0.5f * (acc[mt][nt][2] + xa.x + xb.x) + biasB;
            oo.y = 0.5f * (acc[mt][nt][3] + xa.y + xb.y) + biasB;
            *(float2*)&out[iB] = oo;
        }
    }
}

// =====================================================================
extern "C" void kernel_launch(void* const* d_in, const int* in_sizes, int n_in,
                              void* d_out, int out_size)
{
    const float* x0    = (const float*)d_in[0];
    const float* x1    = (const float*)d_in[1];
    const float* Wq0   = (const float*)d_in[2];
    const float* Wkv0  = (const float*)d_in[3];
    const float* Wq1   = (const float*)d_in[4];
    const float* Wkv1  = (const float*)d_in[5];
    const float* Wout0 = (const float*)d_in[6];
    const float* bout0 = (const float*)d_in[7];
    const float* Wout1 = (const float*)d_in[8];
    const float* bout1 = (const float*)d_in[9];
    float* out = (float*)d_out;

    float *Q0, *Q1, *KV0, *KV1, *O0, *O1;
    cudaGetSymbolAddress((void**)&Q0,  g_Q0);
    cudaGetSymbolAddress((void**)&Q1,  g_Q1);
    cudaGetSymbolAddress((void**)&KV0, g_KV0);
    cudaGetSymbolAddress((void**)&KV1, g_KV1);
    cudaGetSymbolAddress((void**)&O0,  g_O0);
    cudaGetSymbolAddress((void**)&O1,  g_O1);

    cudaFuncSetAttribute(attn_tc, cudaFuncAttributeMaxDynamicSharedMemorySize, ATTN_DSMEM);

    qproj_tc<<<dim3(YD / 128, INNER / 128, 2 * NB), 256>>>(Wq0, x0, Q0, Wq1, x1, Q1);
    kvproj_tc<<<dim3(WW / 128, (2 * INNER) / 128, 2 * NB), 256>>>(Wkv0, x0, KV0, Wkv1, x1, KV1);
    attn_tc<<<dim3(YD / 128, HH, 2 * NB), 256, ATTN_DSMEM>>>(Q0, KV1, O0, Q1, KV0, O1);
    outproj_tc<<<dim3(YD / 128, DIM / 128, NB), 256>>>(
        Wout0, O0, Wout1, O1, bout0, bout1, x0, x1, out);
}